// round 2
// baseline (speedup 1.0000x reference)
#include <cuda_runtime.h>
#include <cstdint>

// ---------------------------------------------------------------------------
// FastTemporalCrosscoder: encode GEMM -> exact top-k -> sparse decode + loss
// ---------------------------------------------------------------------------

#define TPB 256

// Scratch (static device globals — no allocations allowed in kernel_launch)
__device__ float g_pre[(size_t)2048 * 16384];   // pre-activations (B, d_sae)
__device__ int   g_topk_idx[2048 * 256];
__device__ float g_topk_val[2048 * 256];
__device__ float g_partial[2048];

// ------------------------- Encode GEMM (fp32) -----------------------------
// pre = X (M,K) @ W_enc (K,N) + b_enc ; M=2048, N=16384, K=3072
#define BM 128
#define BN 128
#define BKT 16
#define TM 8
#define TN 8

__global__ __launch_bounds__(256, 2)
void sgemm_bias_kernel(const float* __restrict__ A, const float* __restrict__ B,
                       const float* __restrict__ bias,
                       int M, int N, int K)
{
    __shared__ float As[BKT][BM];
    __shared__ float Bs[BKT][BN];
    const int tid  = threadIdx.x;
    const int brow = blockIdx.y * BM;
    const int bcol = blockIdx.x * BN;

    const int a_r = tid >> 2;            // 0..63
    const int a_c = (tid & 3) << 2;      // 0,4,8,12
    const int b_r = tid >> 5;            // 0..7
    const int b_c = (tid & 31) << 2;     // 0..124

    const int ty = tid >> 4;             // 0..15
    const int tx = tid & 15;             // 0..15

    float acc[TM][TN];
#pragma unroll
    for (int i = 0; i < TM; i++)
#pragma unroll
        for (int j = 0; j < TN; j++) acc[i][j] = 0.0f;

    for (int k0 = 0; k0 < K; k0 += BKT) {
#pragma unroll
        for (int p = 0; p < 2; p++) {
            int r = a_r + p * 64;
            float4 v = *(const float4*)(A + (size_t)(brow + r) * K + k0 + a_c);
            As[a_c + 0][r] = v.x;
            As[a_c + 1][r] = v.y;
            As[a_c + 2][r] = v.z;
            As[a_c + 3][r] = v.w;
        }
#pragma unroll
        for (int p = 0; p < 2; p++) {
            int r = b_r + p * 8;
            *(float4*)(&Bs[r][b_c]) =
                *(const float4*)(B + (size_t)(k0 + r) * N + bcol + b_c);
        }
        __syncthreads();
#pragma unroll
        for (int kk = 0; kk < BKT; kk++) {
            float af[TM], bf[TN];
#pragma unroll
            for (int i = 0; i < TM; i += 4)
                *(float4*)&af[i] = *(const float4*)&As[kk][ty * TM + i];
#pragma unroll
            for (int j = 0; j < TN; j += 4)
                *(float4*)&bf[j] = *(const float4*)&Bs[kk][tx * TN + j];
#pragma unroll
            for (int i = 0; i < TM; i++)
#pragma unroll
                for (int j = 0; j < TN; j++)
                    acc[i][j] = fmaf(af[i], bf[j], acc[i][j]);
        }
        __syncthreads();
    }

#pragma unroll
    for (int i = 0; i < TM; i++) {
        int row = brow + ty * TM + i;
#pragma unroll
        for (int j = 0; j < TN; j += 4) {
            int col = bcol + tx * TN + j;
            float4 o;
            o.x = acc[i][j + 0] + bias[col + 0];
            o.y = acc[i][j + 1] + bias[col + 1];
            o.z = acc[i][j + 2] + bias[col + 2];
            o.w = acc[i][j + 3] + bias[col + 3];
            *(float4*)(g_pre + (size_t)row * N + col) = o;
        }
    }
}

// ------------------------- Exact top-k per row -----------------------------
__device__ __forceinline__ unsigned f2ord(float f) {
    unsigned u = __float_as_uint(f);
    return (u & 0x80000000u) ? ~u : (u | 0x80000000u);
}

// one block per row; exact radix-select of k-th largest; deterministic
// index-order tie handling (matches jax.lax.top_k); writes full z row and
// a compacted (idx, relu(val)) list in ascending-index order.
__global__ __launch_bounds__(TPB)
void topk_kernel(const int* __restrict__ kptr, float* __restrict__ z, int n_sae)
{
    const int b = blockIdx.x;
    const float* row = g_pre + (size_t)b * n_sae;
    const int k = kptr[0];
    const int tid = threadIdx.x;
    const int ept = n_sae / TPB;          // 64 contiguous elems per thread

    __shared__ unsigned hist[256];
    __shared__ unsigned s_prefix;
    __shared__ int s_need;
    __shared__ int s_gt[TPB], s_eq[TPB];
    __shared__ int s_gt_base[TPB], s_eq_base[TPB];

    if (tid == 0) { s_prefix = 0u; s_need = k; }
    __syncthreads();

    for (int shift = 24; shift >= 0; shift -= 8) {
        hist[tid] = 0u;
        __syncthreads();
        unsigned pref = s_prefix;
        for (int j = 0; j < ept; j++) {
            unsigned u = f2ord(row[tid * ept + j]);
            bool ok = (shift == 24) ? true : ((u >> (shift + 8)) == pref);
            if (ok) atomicAdd(&hist[(u >> shift) & 255u], 1u);
        }
        __syncthreads();
        if (tid == 0) {
            int need = s_need;
            unsigned cum = 0; int d = 0;
            for (int dd = 255; dd >= 0; dd--) {
                unsigned c = hist[dd];
                if (cum + c >= (unsigned)need) { d = dd; break; }
                cum += c;
            }
            s_need = need - (int)cum;
            s_prefix = (s_prefix << 8) | (unsigned)d;
        }
        __syncthreads();
    }
    const unsigned kth = s_prefix;   // ordered key of k-th largest
    const int need_eq = s_need;      // how many ==kth to take (lowest indices)

    // per-thread counts over this thread's contiguous chunk
    int cgt = 0, ceq = 0;
    for (int j = 0; j < ept; j++) {
        unsigned u = f2ord(row[tid * ept + j]);
        cgt += (u > kth);
        ceq += (u == kth);
    }
    s_gt[tid] = cgt; s_eq[tid] = ceq;
    __syncthreads();
    if (tid == 0) {
        int ag = 0, ae = 0;
        for (int t = 0; t < TPB; t++) {
            s_gt_base[t] = ag; s_eq_base[t] = ae;
            ag += s_gt[t]; ae += s_eq[t];
        }
    }
    __syncthreads();

    const int eq_base = s_eq_base[tid];
    const int base = s_gt_base[tid] + min(need_eq, eq_base);
    int sel = 0, eq_seen = 0;
    float* zrow = z + (size_t)b * n_sae;
    int*   orow = g_topk_idx + b * 256;
    float* vrow = g_topk_val + b * 256;
    for (int j = 0; j < ept; j++) {
        int i = tid * ept + j;
        float f = row[i];
        unsigned u = f2ord(f);
        bool take;
        if (u > kth) take = true;
        else if (u == kth) { take = (eq_base + eq_seen) < need_eq; eq_seen++; }
        else take = false;
        float zv = take ? fmaxf(f, 0.0f) : 0.0f;
        zrow[i] = zv;
        if (take) {
            int slot = base + sel; sel++;
            orow[slot] = i;
            vrow[slot] = zv;
        }
    }
}

// ------------------ Sparse decode + residual squared sums ------------------
// x_hat[b,:] = sum_j val_j * W_dec[idx_j,:] + b_dec ; per-block loss partials.
// Assumes n_td == 3072 (T*d_in), 256 threads, float4 lanes: 768/256 = 3.
// NOTE: x_hat (= d_out + 1) is only 4-byte aligned -> scalar stores only.
__global__ __launch_bounds__(TPB)
void decode_kernel(const float* __restrict__ W_dec, const float* __restrict__ b_dec,
                   const float* __restrict__ x, const int* __restrict__ kptr,
                   float* __restrict__ x_hat, int n_td)
{
    const int b = blockIdx.x;
    const int tid = threadIdx.x;
    const int k = kptr[0];

    __shared__ int   s_idx[256];
    __shared__ float s_val[256];
    if (tid < k) {
        s_idx[tid] = g_topk_idx[b * 256 + tid];
        s_val[tid] = g_topk_val[b * 256 + tid];
    }
    __syncthreads();

    const int n4 = n_td >> 2;   // 768
    float4 acc[3];
#pragma unroll
    for (int q = 0; q < 3; q++) acc[q] = make_float4(0.f, 0.f, 0.f, 0.f);

    for (int j = 0; j < k; j++) {
        const float v = s_val[j];
        const float4* w = (const float4*)(W_dec + (size_t)s_idx[j] * n_td);
#pragma unroll
        for (int q = 0; q < 3; q++) {
            float4 wv = __ldg(&w[tid + 256 * q]);
            acc[q].x = fmaf(v, wv.x, acc[q].x);
            acc[q].y = fmaf(v, wv.y, acc[q].y);
            acc[q].z = fmaf(v, wv.z, acc[q].z);
            acc[q].w = fmaf(v, wv.w, acc[q].w);
        }
    }

    const float4* x4  = (const float4*)(x + (size_t)b * n_td);
    const float4* bd4 = (const float4*)b_dec;
    float* xh = x_hat + (size_t)b * n_td;   // 4B-aligned only
    float sq = 0.0f;
#pragma unroll
    for (int q = 0; q < 3; q++) {
        int p = tid + 256 * q;
        if (p < n4) {
            float4 bb = bd4[p];
            float4 xx = x4[p];
            float ox = acc[q].x + bb.x;
            float oy = acc[q].y + bb.y;
            float oz = acc[q].z + bb.z;
            float ow = acc[q].w + bb.w;
            xh[p * 4 + 0] = ox;
            xh[p * 4 + 1] = oy;
            xh[p * 4 + 2] = oz;
            xh[p * 4 + 3] = ow;
            float dx = ox - xx.x, dy = oy - xx.y, dz = oz - xx.z, dw = ow - xx.w;
            sq += dx * dx + dy * dy + dz * dz + dw * dw;
        }
    }

    __shared__ float red[TPB];
    red[tid] = sq;
    __syncthreads();
    for (int s = TPB / 2; s > 0; s >>= 1) {
        if (tid < s) red[tid] += red[tid + s];
        __syncthreads();
    }
    if (tid == 0) g_partial[b] = red[0];
}

// -------------------------- Loss finalize ----------------------------------
__global__ __launch_bounds__(TPB)
void finalize_kernel(int M, float inv_bt, float* __restrict__ out_loss)
{
    __shared__ float red[TPB];
    const int tid = threadIdx.x;
    float s = 0.0f;
    for (int i = tid; i < M; i += TPB) s += g_partial[i];
    red[tid] = s;
    __syncthreads();
    for (int st = TPB / 2; st > 0; st >>= 1) {
        if (tid < st) red[tid] += red[tid + st];
        __syncthreads();
    }
    if (tid == 0) out_loss[0] = red[0] * inv_bt;
}

// ---------------------------------------------------------------------------
extern "C" void kernel_launch(void* const* d_in, const int* in_sizes, int n_in,
                              void* d_out, int out_size)
{
    const float* x     = (const float*)d_in[0];   // (B, T, d_in)
    const float* W_enc = (const float*)d_in[1];   // (T, d_in, d_sae)
    const float* b_enc = (const float*)d_in[2];   // (d_sae)
    const float* W_dec = (const float*)d_in[3];   // (d_sae, T, d_in)
    const float* b_dec = (const float*)d_in[4];   // (T, d_in)
    const int*   kptr  = (const int*)d_in[5];     // scalar k

    const int n_td = in_sizes[4];                 // T*d_in = 3072
    const int M    = in_sizes[0] / n_td;          // B = 2048
    const int N    = in_sizes[2];                 // d_sae = 16384
    const int BT   = in_sizes[0] / 768;           // B*T = 8192 (d_in = 768)

    float* out      = (float*)d_out;
    float* out_loss = out;                        // scalar
    float* out_xhat = out + 1;                    // (B, T, d_in)
    float* out_z    = out + 1 + (size_t)M * n_td; // (B, d_sae)

    dim3 gemm_grid(N / BN, M / BM);
    sgemm_bias_kernel<<<gemm_grid, 256>>>(x, W_enc, b_enc, M, N, n_td);
    topk_kernel<<<M, TPB>>>(kptr, out_z, N);
    decode_kernel<<<M, TPB>>>(W_dec, b_dec, x, kptr, out_xhat, n_td);
    finalize_kernel<<<1, TPB>>>(M, 1.0f / (float)BT, out_loss);
}